// round 7
// baseline (speedup 1.0000x reference)
#include <cuda_runtime.h>
#include <cuda_fp16.h>
#include <cstdint>
#include <math.h>

// ---------------- problem constants ----------------
#define S_LEN 2048
#define BHN   64          // B*H
#define DQ    64
#define DP    32
#define KC    96          // concatenated K (q|pq)
#define SCALE_Q 0.125f
#define SCALE_P 0.17677669529663687f

#define MROWS 16          // rows per CTA (full 2048-wide ownership)
#define NSUB  128         // columns per subtile
#define NSUBS 16          // 2048 / 128
#define SPADB 208         // smem row stride bytes (104 halves = 13*16B, conflict-free)
#define BSLOT (NSUB * SPADB)          // 26624 B per B ring slot
#define SM_A   0
#define SM_RED 3328                   // after A (16*208): 16*16 partials + 16 sums
#define SM_B   4480                   // 3328 + 1088, 16B aligned
#define SM_TOT (SM_B + 4 * BSLOT)     // 110976 B

// fp16 scratch: [bh][s][96]  (clamp+scale folded on A side)
__device__ __align__(16) __half g_Ah[(size_t)BHN * S_LEN * KC];
__device__ __align__(16) __half g_Bh[(size_t)BHN * S_LEN * KC];

__device__ __forceinline__ float clamp5(float x) {
    return fminf(fmaxf(x, -5.0f), 5.0f);
}

__device__ __forceinline__ uint32_t smem_u32(const void* p) {
    uint32_t a;
    asm("{ .reg .u64 t; cvta.to.shared.u64 t, %1; cvt.u32.u64 %0, t; }" : "=r"(a) : "l"(p));
    return a;
}
__device__ __forceinline__ void cp16(uint32_t dst, const void* src) {
    asm volatile("cp.async.cg.shared.global [%0], [%1], 16;" :: "r"(dst), "l"(src));
}
#define CP_COMMIT() asm volatile("cp.async.commit_group;" ::: "memory")
#define CP_WAIT2()  asm volatile("cp.async.wait_group 2;" ::: "memory")

__device__ __forceinline__ void ldsm_x4(uint32_t* r, uint32_t addr) {
    asm volatile("ldmatrix.sync.aligned.m8n8.x4.shared.b16 {%0,%1,%2,%3}, [%4];"
                 : "=r"(r[0]), "=r"(r[1]), "=r"(r[2]), "=r"(r[3]) : "r"(addr));
}
__device__ __forceinline__ void ldsm_x2(uint32_t* r, uint32_t addr) {
    asm volatile("ldmatrix.sync.aligned.m8n8.x2.shared.b16 {%0,%1}, [%2];"
                 : "=r"(r[0]), "=r"(r[1]) : "r"(addr));
}
__device__ __forceinline__ void mma_fp16(float* d, const uint32_t* a, const uint32_t* b) {
    asm volatile("mma.sync.aligned.m16n8k16.row.col.f32.f16.f16.f32 "
                 "{%0,%1,%2,%3}, {%4,%5,%6,%7}, {%8,%9}, {%0,%1,%2,%3};"
                 : "+f"(d[0]), "+f"(d[1]), "+f"(d[2]), "+f"(d[3])
                 : "r"(a[0]), "r"(a[1]), "r"(a[2]), "r"(a[3]), "r"(b[0]), "r"(b[1]));
}

// pure-FMA exp (poly exp2); inputs bounded (|score| <~ 10). MUFU avoided.
__device__ __forceinline__ float fast_exp(float x) {
    float y = x * 1.4426950408889634f;
    float n = rintf(y);
    float f = y - n;
    float p = 1.5403530393e-4f;
    p = fmaf(p, f, 1.3333558146e-3f);
    p = fmaf(p, f, 9.6181291076e-3f);
    p = fmaf(p, f, 5.5504108664e-2f);
    p = fmaf(p, f, 2.4022650696e-1f);
    p = fmaf(p, f, 6.9314718056e-1f);
    p = fmaf(p, f, 1.0f);
    int e = (int)n + 127;
    float s = (e > 0) ? __int_as_float(e << 23) : 0.0f;
    return p * s;
}

// ---------------------------------------------------------------------------
// Pass 0: clamp + scale + fp16 convert into K-concatenated scratch.
// ---------------------------------------------------------------------------
__global__ __launch_bounds__(256) void prep_fp16(
    const float* __restrict__ keys, const float* __restrict__ queries,
    const float* __restrict__ pos_key, const float* __restrict__ pos_query)
{
    size_t idx = (size_t)blockIdx.x * blockDim.x + threadIdx.x;
    const size_t total = (size_t)BHN * S_LEN * KC;
    if (idx >= total) return;
    size_t row = idx / KC;
    int c = (int)(idx % KC);
    float a, b;
    if (c < DQ) {
        a = clamp5(queries[row * DQ + c]) * SCALE_Q;
        b = clamp5(keys[row * DQ + c]);
    } else {
        a = clamp5(pos_query[row * DP + (c - DQ)]) * SCALE_P;
        b = clamp5(pos_key[row * DP + (c - DQ)]);
    }
    g_Ah[idx] = __float2half_rn(a);
    g_Bh[idx] = __float2half_rn(b);
}

// ---------------------------------------------------------------------------
// Pass 1 (fused): 16x2048 scores in registers -> exp -> rowsum -> normalized
// write. Single DRAM pass for the output.
// cp.async ledger invariant: 3 groups committed in prologue, exactly ONE
// group committed per loop iteration (empty when no prefetch remains), so
// wait_group 2 at iter s always guarantees group s (B[s]) has landed.
// ---------------------------------------------------------------------------
__global__ __launch_bounds__(512, 1) void fused_attn(float* __restrict__ out)
{
    extern __shared__ __align__(16) char smraw[];
    float* redp = (float*)(smraw + SM_RED);          // [16 rows][16 warps] partials
    float* rsum = redp + 16 * 16;                    // [16] final inverse sums
    const uint32_t sA = smem_u32(smraw + SM_A);
    const uint32_t sB = smem_u32(smraw + SM_B);

    const int tid = threadIdx.x;
    const int lane = tid & 31, warp = tid >> 5;     // 16 warps
    const int mt = blockIdx.x, bh = blockIdx.y;

    const __half* Ag = g_Ah + ((size_t)bh * S_LEN + (size_t)mt * MROWS) * KC;
    const __half* Bg = g_Bh + (size_t)bh * S_LEN * KC;

    // --- group 0: A (192 chunks) + B0; groups 1, 2: B1, B2 ---
    if (tid < 192) {
        int row = tid / 12, c = tid % 12;
        cp16(sA + row * SPADB + c * 16, (const char*)Ag + (size_t)row * (KC * 2) + c * 16);
    }
    #pragma unroll
    for (int i = 0; i < 3; i++) {            // B0: 1536 chunks, 3/thread
        int f = tid + i * 512;
        int row = f / 12, c = f % 12;
        cp16(sB + row * SPADB + c * 16, (const char*)Bg + (size_t)row * (KC * 2) + c * 16);
    }
    CP_COMMIT();
    #pragma unroll
    for (int j = 1; j <= 2; j++) {
        #pragma unroll
        for (int i = 0; i < 3; i++) {
            int f = tid + i * 512;
            int row = f / 12, c = f % 12;
            cp16(sB + (j & 3) * BSLOT + row * SPADB + c * 16,
                 (const char*)Bg + ((size_t)j * NSUB + row) * (KC * 2) + c * 16);
        }
        CP_COMMIT();
    }

    CP_WAIT2();                 // group 0 (A + B0) complete
    __syncthreads();

    // --- A fragments: 6 k-steps, shared by all warps (broadcast reads) ---
    uint32_t aF[6][4];
    {
        const uint32_t abase = sA + (lane & 15) * SPADB + ((lane >> 4) << 3) * 2;
        #pragma unroll
        for (int k = 0; k < 6; k++)
            ldsm_x4(aF[k], abase + k * 32);
    }

    const int r0 = lane >> 2;                       // fragment rows r0, r0+8
    const uint32_t bfrag_off = (warp * 8 + (lane & 7)) * SPADB + (((lane >> 3) & 1) << 3) * 2;

    float sc[NSUBS][4];
    float s0 = 0.0f, s1 = 0.0f;

    #pragma unroll
    for (int s = 0; s < NSUBS; s++) {
        if (s > 0) { CP_WAIT2(); __syncthreads(); }  // B[s] landed; s-1 reads done CTA-wide

        const uint32_t bb = sB + (s & 3) * BSLOT + bfrag_off;
        uint32_t b[6][2];
        #pragma unroll
        for (int k = 0; k < 6; k++)
            ldsm_x2(b[k], bb + k * 32);

        float acc[4] = { 0.0f, 0.0f, 0.0f, 0.0f };
        #pragma unroll
        for (int k = 0; k < 6; k++)
            mma_fp16(acc, aF[k], b[k]);

        // prefetch B[s+3] into slot freed at iter s-1; ALWAYS commit one group
        if (s + 3 < NSUBS) {
            #pragma unroll
            for (int i = 0; i < 3; i++) {
                int f = tid + i * 512;
                int row = f / 12, c = f % 12;
                cp16(sB + ((s + 3) & 3) * BSLOT + row * SPADB + c * 16,
                     (const char*)Bg + ((size_t)(s + 3) * NSUB + row) * (KC * 2) + c * 16);
            }
        }
        CP_COMMIT();   // unconditional: keeps the wait_group 2 ledger uniform

        sc[s][0] = fast_exp(acc[0]);
        sc[s][1] = fast_exp(acc[1]);
        sc[s][2] = fast_exp(acc[2]);
        sc[s][3] = fast_exp(acc[3]);
        s0 += sc[s][0] + sc[s][1];
        s1 += sc[s][2] + sc[s][3];
    }

    // --- deterministic row sums: quad shuffle -> per-warp partials -> 16 adders
    s0 += __shfl_xor_sync(0xffffffffu, s0, 1);
    s0 += __shfl_xor_sync(0xffffffffu, s0, 2);
    s1 += __shfl_xor_sync(0xffffffffu, s1, 1);
    s1 += __shfl_xor_sync(0xffffffffu, s1, 2);
    if ((lane & 3) == 0) {                    // 8 quad leaders: r0 = 0..7
        redp[r0 * 16 + warp] = s0;            // rows 0-7
        redp[(r0 + 8) * 16 + warp] = s1;      // rows 8-15
    }
    __syncthreads();
    if (tid < MROWS) {
        float t = 0.0f;
        #pragma unroll
        for (int w = 0; w < 16; w++) t += redp[tid * 16 + w];
        rsum[tid] = 1.0f / t;
    }
    __syncthreads();

    const float inv0 = rsum[r0];
    const float inv1 = rsum[r0 + 8];

    // --- normalized writes: the only DRAM output pass ---
    const size_t rowg0 = ((size_t)bh * S_LEN + (size_t)mt * MROWS + r0) * S_LEN;
    const int coloff = warp * 8 + (lane & 3) * 2;
    #pragma unroll
    for (int s = 0; s < NSUBS; s++) {
        const int col = s * NSUB + coloff;
        *(float2*)(out + rowg0 + col) = make_float2(sc[s][0] * inv0, sc[s][1] * inv0);
        *(float2*)(out + rowg0 + (size_t)8 * S_LEN + col) =
            make_float2(sc[s][2] * inv1, sc[s][3] * inv1);
    }
}

// ---------------------------------------------------------------------------
extern "C" void kernel_launch(void* const* d_in, const int* in_sizes, int n_in,
                              void* d_out, int out_size)
{
    const float* keys      = (const float*)d_in[0];
    const float* queries   = (const float*)d_in[1];
    const float* pos_key   = (const float*)d_in[2];
    const float* pos_query = (const float*)d_in[3];
    float* out = (float*)d_out;

    // pass 0: fp16 convert
    const size_t prep_total = (size_t)BHN * S_LEN * KC;
    prep_fp16<<<(unsigned)((prep_total + 255) / 256), 256>>>(keys, queries, pos_key, pos_query);

    // pass 1: fused GEMM + softmax
    cudaFuncSetAttribute(fused_attn, cudaFuncAttributeMaxDynamicSharedMemorySize, SM_TOT);
    dim3 g(S_LEN / MROWS, BHN);     // (128, 64)
    fused_attn<<<g, 512, SM_TOT>>>(out);
}

// round 8
// speedup vs baseline: 1.0319x; 1.0319x over previous
#include <cuda_runtime.h>
#include <cuda_fp16.h>
#include <cstdint>
#include <math.h>

// ---------------- problem constants ----------------
#define S_LEN 2048
#define BHN   64          // B*H
#define DQ    64
#define DP    32
#define KC    96          // concatenated K (q|pq)
#define SCALE_Q 0.125f
#define SCALE_P 0.17677669529663687f

#define MROWS 16          // rows per CTA (full 2048-wide ownership)
#define NSUB  128         // columns per subtile
#define NSUBS 16          // 2048 / 128
#define SPADB 208         // smem row stride bytes (13*16B, ldmatrix conflict-free)
#define WSTAGE 1664       // per-warp per-stage bytes (8 rows * 208)
#define WSLAB  (4 * WSTAGE)           // 6656 B per warp (4 stages)
#define SM_A   0                      // A: 16 * 208 = 3328
#define SM_RED 3328                   // 16*16 partials + 16 sums = 1088
#define SM_B   4416                   // 16B aligned
#define SM_TOT (SM_B + 16 * WSLAB)    // 110912 B

// fp16 scratch: [bh][s][96]  (clamp+scale folded on A side)
__device__ __align__(16) __half g_Ah[(size_t)BHN * S_LEN * KC];
__device__ __align__(16) __half g_Bh[(size_t)BHN * S_LEN * KC];

__device__ __forceinline__ float clamp5(float x) {
    return fminf(fmaxf(x, -5.0f), 5.0f);
}

__device__ __forceinline__ uint32_t smem_u32(const void* p) {
    uint32_t a;
    asm("{ .reg .u64 t; cvta.to.shared.u64 t, %1; cvt.u32.u64 %0, t; }" : "=r"(a) : "l"(p));
    return a;
}
__device__ __forceinline__ void cp16(uint32_t dst, const void* src) {
    asm volatile("cp.async.cg.shared.global [%0], [%1], 16;" :: "r"(dst), "l"(src));
}
#define CP_COMMIT() asm volatile("cp.async.commit_group;" ::: "memory")
#define CP_WAIT2()  asm volatile("cp.async.wait_group 2;" ::: "memory")

__device__ __forceinline__ void ldsm_x4(uint32_t* r, uint32_t addr) {
    asm volatile("ldmatrix.sync.aligned.m8n8.x4.shared.b16 {%0,%1,%2,%3}, [%4];"
                 : "=r"(r[0]), "=r"(r[1]), "=r"(r[2]), "=r"(r[3]) : "r"(addr));
}
__device__ __forceinline__ void mma_fp16(float* d, const uint32_t* a, const uint32_t* b) {
    asm volatile("mma.sync.aligned.m16n8k16.row.col.f32.f16.f16.f32 "
                 "{%0,%1,%2,%3}, {%4,%5,%6,%7}, {%8,%9}, {%0,%1,%2,%3};"
                 : "+f"(d[0]), "+f"(d[1]), "+f"(d[2]), "+f"(d[3])
                 : "r"(a[0]), "r"(a[1]), "r"(a[2]), "r"(a[3]), "r"(b[0]), "r"(b[1]));
}

// pure-FMA exp (poly exp2); inputs bounded (|score| <~ 10). MUFU avoided.
__device__ __forceinline__ float fast_exp(float x) {
    float y = x * 1.4426950408889634f;
    float n = rintf(y);
    float f = y - n;
    float p = 1.5403530393e-4f;
    p = fmaf(p, f, 1.3333558146e-3f);
    p = fmaf(p, f, 9.6181291076e-3f);
    p = fmaf(p, f, 5.5504108664e-2f);
    p = fmaf(p, f, 2.4022650696e-1f);
    p = fmaf(p, f, 6.9314718056e-1f);
    p = fmaf(p, f, 1.0f);
    int e = (int)n + 127;
    float s = (e > 0) ? __int_as_float(e << 23) : 0.0f;
    return p * s;
}

// ---------------------------------------------------------------------------
// Pass 0: clamp + scale + fp16 convert into K-concatenated scratch.
// ---------------------------------------------------------------------------
__global__ __launch_bounds__(256) void prep_fp16(
    const float* __restrict__ keys, const float* __restrict__ queries,
    const float* __restrict__ pos_key, const float* __restrict__ pos_query)
{
    size_t idx = (size_t)blockIdx.x * blockDim.x + threadIdx.x;
    const size_t total = (size_t)BHN * S_LEN * KC;
    if (idx >= total) return;
    size_t row = idx / KC;
    int c = (int)(idx % KC);
    float a, b;
    if (c < DQ) {
        a = clamp5(queries[row * DQ + c]) * SCALE_Q;
        b = clamp5(keys[row * DQ + c]);
    } else {
        a = clamp5(pos_query[row * DP + (c - DQ)]) * SCALE_P;
        b = clamp5(pos_key[row * DP + (c - DQ)]);
    }
    g_Ah[idx] = __float2half_rn(a);
    g_Bh[idx] = __float2half_rn(b);
}

// ---------------------------------------------------------------------------
// Pass 1 (fused): 16x2048 scores in registers -> exp -> rowsum -> normalized
// write. Warp-private B pipelines: each warp streams ONLY its own 8 B-rows
// per subtile through a private 4-stage smem ring (own cp.async groups), so
// the hot loop has NO CTA barrier — just wait_group + syncwarp.
// Ledger: 3 groups in prologue, exactly one commit per iter -> at iter s,
// wait_group 2 guarantees stage s landed.
// ---------------------------------------------------------------------------
__global__ __launch_bounds__(512, 1) void fused_attn(float* __restrict__ out)
{
    extern __shared__ __align__(16) char smraw[];
    float* redp = (float*)(smraw + SM_RED);          // [16 rows][16 warps]
    float* rsum = redp + 16 * 16;                    // [16] inverse sums
    const uint32_t sA = smem_u32(smraw + SM_A);

    const int tid = threadIdx.x;
    const int lane = tid & 31, warp = tid >> 5;     // 16 warps
    const int mt = blockIdx.x, bh = blockIdx.y;

    const __half* Ag = g_Ah + ((size_t)bh * S_LEN + (size_t)mt * MROWS) * KC;
    const __half* Bg = g_Bh + (size_t)bh * S_LEN * KC;

    const uint32_t slab = smem_u32(smraw + SM_B) + warp * WSLAB;

    // per-lane B chunk coords (3 chunks of 16B per lane per stage)
    const int br0 = lane / 12 + ((lane % 12) == lane ? 0 : 0); // (placeholder, computed below)

    // --- prologue: issue B stages 0,1,2 (per-warp groups) ---
    #pragma unroll
    for (int j = 0; j < 3; j++) {
        #pragma unroll
        for (int i = 0; i < 3; i++) {
            int f = lane + i * 32;            // 0..95
            int r = f / 12, c = f % 12;
            cp16(slab + j * WSTAGE + r * SPADB + c * 16,
                 (const char*)Bg + ((size_t)j * NSUB + warp * 8 + r) * (KC * 2) + c * 16);
        }
        CP_COMMIT();
    }

    // --- A: 192 chunks via plain ld/st (one-time), then CTA barrier ---
    if (tid < 192) {
        int row = tid / 12, c = tid % 12;
        uint4 v = *(const uint4*)((const char*)Ag + (size_t)row * (KC * 2) + c * 16);
        *(uint4*)(smraw + SM_A + row * SPADB + c * 16) = v;
    }
    __syncthreads();

    // --- A fragments: 6 k-steps (broadcast reads, conflict-free) ---
    uint32_t aF[6][4];
    {
        const uint32_t abase = sA + (lane & 15) * SPADB + ((lane >> 4) << 3) * 2;
        #pragma unroll
        for (int k = 0; k < 6; k++)
            ldsm_x4(aF[k], abase + k * 32);
    }

    const int r0 = lane >> 2;                       // fragment rows r0, r0+8
    // B frag base within a stage: local row = lane&7, col group = lane>>3 (0..3)
    const uint32_t bfoff = (lane & 7) * SPADB + (lane >> 3) * 16;

    float sc[NSUBS][4];
    float s0 = 0.0f, s1 = 0.0f;

    #pragma unroll
    for (int s = 0; s < NSUBS; s++) {
        CP_WAIT2();                     // stage s landed (per-thread ledger)
        __syncwarp();                   // make all lanes' copies visible warp-wide

        const uint32_t bb = slab + (s & 3) * WSTAGE + bfoff;
        // 3 x ldsm_x4: each yields b-frags for two k-steps
        uint32_t b[3][4];
        #pragma unroll
        for (int j = 0; j < 3; j++)
            ldsm_x4(b[j], bb + j * 64);

        // two independent accumulator chains (alternating k-steps)
        float accA[4] = { 0.0f, 0.0f, 0.0f, 0.0f };
        float accB[4] = { 0.0f, 0.0f, 0.0f, 0.0f };
        #pragma unroll
        for (int j = 0; j < 3; j++) {
            mma_fp16(accA, aF[2 * j],     &b[j][0]);
            mma_fp16(accB, aF[2 * j + 1], &b[j][2]);
        }

        // prefetch stage s+3 into slot consumed at iter s-1; one commit per iter
        if (s + 3 < NSUBS) {
            #pragma unroll
            for (int i = 0; i < 3; i++) {
                int f = lane + i * 32;
                int r = f / 12, c = f % 12;
                cp16(slab + ((s + 3) & 3) * WSTAGE + r * SPADB + c * 16,
                     (const char*)Bg + ((size_t)(s + 3) * NSUB + warp * 8 + r) * (KC * 2) + c * 16);
            }
        }
        CP_COMMIT();

        sc[s][0] = fast_exp(accA[0] + accB[0]);
        sc[s][1] = fast_exp(accA[1] + accB[1]);
        sc[s][2] = fast_exp(accA[2] + accB[2]);
        sc[s][3] = fast_exp(accA[3] + accB[3]);
        s0 += sc[s][0] + sc[s][1];
        s1 += sc[s][2] + sc[s][3];
    }

    // --- deterministic row sums: quad shuffle -> warp partials -> 16 adders ---
    s0 += __shfl_xor_sync(0xffffffffu, s0, 1);
    s0 += __shfl_xor_sync(0xffffffffu, s0, 2);
    s1 += __shfl_xor_sync(0xffffffffu, s1, 1);
    s1 += __shfl_xor_sync(0xffffffffu, s1, 2);
    if ((lane & 3) == 0) {                    // quad leaders: r0 = 0..7
        redp[r0 * 16 + warp] = s0;            // rows 0-7
        redp[(r0 + 8) * 16 + warp] = s1;      // rows 8-15
    }
    __syncthreads();
    if (tid < MROWS) {
        float t = 0.0f;
        #pragma unroll
        for (int w = 0; w < 16; w++) t += redp[tid * 16 + w];
        rsum[tid] = 1.0f / t;
    }
    __syncthreads();

    const float inv0 = rsum[r0];
    const float inv1 = rsum[r0 + 8];

    // --- normalized writes: the only DRAM output pass ---
    const size_t rowg0 = ((size_t)bh * S_LEN + (size_t)mt * MROWS + r0) * S_LEN;
    const int coloff = warp * 8 + (lane & 3) * 2;
    #pragma unroll
    for (int s = 0; s < NSUBS; s++) {
        const int col = s * NSUB + coloff;
        *(float2*)(out + rowg0 + col) = make_float2(sc[s][0] * inv0, sc[s][1] * inv0);
        *(float2*)(out + rowg0 + (size_t)8 * S_LEN + col) =
            make_float2(sc[s][2] * inv1, sc[s][3] * inv1);
    }
}

// ---------------------------------------------------------------------------
extern "C" void kernel_launch(void* const* d_in, const int* in_sizes, int n_in,
                              void* d_out, int out_size)
{
    const float* keys      = (const float*)d_in[0];
    const float* queries   = (const float*)d_in[1];
    const float* pos_key   = (const float*)d_in[2];
    const float* pos_query = (const float*)d_in[3];
    float* out = (float*)d_out;

    // pass 0: fp16 convert
    const size_t prep_total = (size_t)BHN * S_LEN * KC;
    prep_fp16<<<(unsigned)((prep_total + 255) / 256), 256>>>(keys, queries, pos_key, pos_query);

    // pass 1: fused GEMM + softmax
    cudaFuncSetAttribute(fused_attn, cudaFuncAttributeMaxDynamicSharedMemorySize, SM_TOT);
    dim3 g(S_LEN / MROWS, BHN);     // (128, 64)
    fused_attn<<<g, 512, SM_TOT>>>(out);
}

// round 9
// speedup vs baseline: 1.1765x; 1.1402x over previous
#include <cuda_runtime.h>
#include <cuda_fp16.h>
#include <cstdint>
#include <math.h>

// ---------------- problem constants ----------------
#define S_LEN 2048
#define BHN   64          // B*H
#define DQ    64
#define DP    32
#define KC    96          // concatenated K (q|pq)
#define SCALE_Q 0.125f
#define SCALE_P 0.17677669529663687f

#define MROWS 16          // rows per CTA (full 2048-wide ownership)
#define NSUB  128         // columns per subtile
#define NSUBS 16          // 2048 / 128
#define SPADB 208         // smem row stride bytes (13*16B, ldmatrix conflict-free)
#define NSTG  6           // B ring stages per warp
#define WSTAGE 1664       // per-warp per-stage bytes (8 rows * 208)
#define WSLAB  (NSTG * WSTAGE)        // 9984 B per warp
#define SM_A   0                      // A: 16 * 208 = 3328
#define SM_RED 3328                   // 16*16 partials + 16 sums = 1088
#define SM_B   4416                   // 16B aligned
#define SM_TOT (SM_B + 16 * WSLAB)    // 164160 B

// fp16 scratch: [bh][s][96]  (clamp+scale folded on A side)
__device__ __align__(16) __half g_Ah[(size_t)BHN * S_LEN * KC];
__device__ __align__(16) __half g_Bh[(size_t)BHN * S_LEN * KC];

__device__ __forceinline__ float clamp5(float x) {
    return fminf(fmaxf(x, -5.0f), 5.0f);
}

__device__ __forceinline__ uint32_t smem_u32(const void* p) {
    uint32_t a;
    asm("{ .reg .u64 t; cvta.to.shared.u64 t, %1; cvt.u32.u64 %0, t; }" : "=r"(a) : "l"(p));
    return a;
}
__device__ __forceinline__ void cp16(uint32_t dst, const void* src) {
    asm volatile("cp.async.cg.shared.global [%0], [%1], 16;" :: "r"(dst), "l"(src));
}
#define CP_COMMIT() asm volatile("cp.async.commit_group;" ::: "memory")
#define CP_WAIT4()  asm volatile("cp.async.wait_group 4;" ::: "memory")

__device__ __forceinline__ void ldsm_x4(uint32_t* r, uint32_t addr) {
    asm volatile("ldmatrix.sync.aligned.m8n8.x4.shared.b16 {%0,%1,%2,%3}, [%4];"
                 : "=r"(r[0]), "=r"(r[1]), "=r"(r[2]), "=r"(r[3]) : "r"(addr));
}
__device__ __forceinline__ void mma_fp16(float* d, const uint32_t* a, const uint32_t* b) {
    asm volatile("mma.sync.aligned.m16n8k16.row.col.f32.f16.f16.f32 "
                 "{%0,%1,%2,%3}, {%4,%5,%6,%7}, {%8,%9}, {%0,%1,%2,%3};"
                 : "+f"(d[0]), "+f"(d[1]), "+f"(d[2]), "+f"(d[3])
                 : "r"(a[0]), "r"(a[1]), "r"(a[2]), "r"(a[3]), "r"(b[0]), "r"(b[1]));
}

// ---------------------------------------------------------------------------
// Pass 0: clamp + scale + fp16 convert; 4 elements per thread (float4 loads).
// ---------------------------------------------------------------------------
__global__ __launch_bounds__(256) void prep_fp16(
    const float* __restrict__ keys, const float* __restrict__ queries,
    const float* __restrict__ pos_key, const float* __restrict__ pos_query)
{
    size_t idx4 = (size_t)blockIdx.x * blockDim.x + threadIdx.x;
    const size_t total4 = (size_t)BHN * S_LEN * (KC / 4);
    if (idx4 >= total4) return;
    size_t row = idx4 / (KC / 4);
    int q = (int)(idx4 % (KC / 4));
    int c0 = q * 4;
    float4 va, vb;
    if (c0 < DQ) {
        va = *(const float4*)(queries + row * DQ + c0);
        vb = *(const float4*)(keys + row * DQ + c0);
        va.x = clamp5(va.x) * SCALE_Q; va.y = clamp5(va.y) * SCALE_Q;
        va.z = clamp5(va.z) * SCALE_Q; va.w = clamp5(va.w) * SCALE_Q;
        vb.x = clamp5(vb.x); vb.y = clamp5(vb.y);
        vb.z = clamp5(vb.z); vb.w = clamp5(vb.w);
    } else {
        va = *(const float4*)(pos_query + row * DP + (c0 - DQ));
        vb = *(const float4*)(pos_key + row * DP + (c0 - DQ));
        va.x = clamp5(va.x) * SCALE_P; va.y = clamp5(va.y) * SCALE_P;
        va.z = clamp5(va.z) * SCALE_P; va.w = clamp5(va.w) * SCALE_P;
        vb.x = clamp5(vb.x); vb.y = clamp5(vb.y);
        vb.z = clamp5(vb.z); vb.w = clamp5(vb.w);
    }
    __half2 a01 = __floats2half2_rn(va.x, va.y), a23 = __floats2half2_rn(va.z, va.w);
    __half2 b01 = __floats2half2_rn(vb.x, vb.y), b23 = __floats2half2_rn(vb.z, vb.w);
    *(__half2*)(g_Ah + row * KC + c0)     = a01;
    *(__half2*)(g_Ah + row * KC + c0 + 2) = a23;
    *(__half2*)(g_Bh + row * KC + c0)     = b01;
    *(__half2*)(g_Bh + row * KC + c0 + 2) = b23;
}

// ---------------------------------------------------------------------------
// Pass 1 (fused): 16x2048 scores in registers -> exp -> rowsum -> normalized
// write. Warp-private 6-stage B ring (prefetch distance 5 covers L2/LDGSTS
// completion latency ~600-1000cyc); exp via MUFU (__expf).
// Ledger: 5 groups in prologue, one commit per iter -> at iter s,
// wait_group 4 guarantees stage s landed.
// ---------------------------------------------------------------------------
__global__ __launch_bounds__(512, 1) void fused_attn(float* __restrict__ out)
{
    extern __shared__ __align__(16) char smraw[];
    float* redp = (float*)(smraw + SM_RED);          // [16 rows][16 warps]
    float* rsum = redp + 16 * 16;                    // [16] inverse sums
    const uint32_t sA = smem_u32(smraw + SM_A);

    const int tid = threadIdx.x;
    const int lane = tid & 31, warp = tid >> 5;     // 16 warps
    const int mt = blockIdx.x, bh = blockIdx.y;

    const __half* Ag = g_Ah + ((size_t)bh * S_LEN + (size_t)mt * MROWS) * KC;
    const __half* Bg = g_Bh + (size_t)bh * S_LEN * KC;

    const uint32_t slab = smem_u32(smraw + SM_B) + warp * WSLAB;

    // --- prologue: issue B stages 0..4 (per-warp groups) ---
    #pragma unroll
    for (int j = 0; j < 5; j++) {
        #pragma unroll
        for (int i = 0; i < 3; i++) {
            int f = lane + i * 32;            // 0..95
            int r = f / 12, c = f % 12;
            cp16(slab + j * WSTAGE + r * SPADB + c * 16,
                 (const char*)Bg + ((size_t)j * NSUB + warp * 8 + r) * (KC * 2) + c * 16);
        }
        CP_COMMIT();
    }

    // --- A: 192 chunks via plain ld/st (one-time), then CTA barrier ---
    if (tid < 192) {
        int row = tid / 12, c = tid % 12;
        uint4 v = *(const uint4*)((const char*)Ag + (size_t)row * (KC * 2) + c * 16);
        *(uint4*)(smraw + SM_A + row * SPADB + c * 16) = v;
    }
    __syncthreads();

    // --- A fragments: 6 k-steps (broadcast reads, conflict-free) ---
    uint32_t aF[6][4];
    {
        const uint32_t abase = sA + (lane & 15) * SPADB + ((lane >> 4) << 3) * 2;
        #pragma unroll
        for (int k = 0; k < 6; k++)
            ldsm_x4(aF[k], abase + k * 32);
    }

    const int r0 = lane >> 2;                       // fragment rows r0, r0+8
    // B frag base within a stage: local row = lane&7, col group = lane>>3 (0..3)
    const uint32_t bfoff = (lane & 7) * SPADB + (lane >> 3) * 16;

    float sc[NSUBS][4];
    float s0 = 0.0f, s1 = 0.0f;

    #pragma unroll
    for (int s = 0; s < NSUBS; s++) {
        CP_WAIT4();                     // stage s landed (5+s committed, newest 4 may pend)
        __syncwarp();                   // all lanes' copies visible warp-wide

        const uint32_t bb = slab + (s % NSTG) * WSTAGE + bfoff;
        // 3 x ldsm_x4: each yields b-frags for two k-steps
        uint32_t b[3][4];
        #pragma unroll
        for (int j = 0; j < 3; j++)
            ldsm_x4(b[j], bb + j * 64);

        // two independent accumulator chains (alternating k-steps)
        float accA[4] = { 0.0f, 0.0f, 0.0f, 0.0f };
        float accB[4] = { 0.0f, 0.0f, 0.0f, 0.0f };
        #pragma unroll
        for (int j = 0; j < 3; j++) {
            mma_fp16(accA, aF[2 * j],     &b[j][0]);
            mma_fp16(accB, aF[2 * j + 1], &b[j][2]);
        }

        // prefetch stage s+5 into slot consumed at iter s-1; one commit per iter
        if (s + 5 < NSUBS) {
            #pragma unroll
            for (int i = 0; i < 3; i++) {
                int f = lane + i * 32;
                int r = f / 12, c = f % 12;
                cp16(slab + ((s + 5) % NSTG) * WSTAGE + r * SPADB + c * 16,
                     (const char*)Bg + ((size_t)(s + 5) * NSUB + warp * 8 + r) * (KC * 2) + c * 16);
            }
        }
        CP_COMMIT();

        // exp via MUFU.EX2 (2 instrs each, no serial FMA chain)
        sc[s][0] = __expf(accA[0] + accB[0]);
        sc[s][1] = __expf(accA[1] + accB[1]);
        sc[s][2] = __expf(accA[2] + accB[2]);
        sc[s][3] = __expf(accA[3] + accB[3]);
        s0 += sc[s][0] + sc[s][1];
        s1 += sc[s][2] + sc[s][3];
    }

    // --- deterministic row sums: quad shuffle -> warp partials -> 16 adders ---
    s0 += __shfl_xor_sync(0xffffffffu, s0, 1);
    s0 += __shfl_xor_sync(0xffffffffu, s0, 2);
    s1 += __shfl_xor_sync(0xffffffffu, s1, 1);
    s1 += __shfl_xor_sync(0xffffffffu, s1, 2);
    if ((lane & 3) == 0) {                    // quad leaders: r0 = 0..7
        redp[r0 * 16 + warp] = s0;            // rows 0-7
        redp[(r0 + 8) * 16 + warp] = s1;      // rows 8-15
    }
    __syncthreads();
    if (tid < MROWS) {
        float t = 0.0f;
        #pragma unroll
        for (int w = 0; w < 16; w++) t += redp[tid * 16 + w];
        rsum[tid] = 1.0f / t;
    }
    __syncthreads();

    const float inv0 = rsum[r0];
    const float inv1 = rsum[r0 + 8];

    // --- normalized writes: the only DRAM output pass ---
    const size_t rowg0 = ((size_t)bh * S_LEN + (size_t)mt * MROWS + r0) * S_LEN;
    const int coloff = warp * 8 + (lane & 3) * 2;
    #pragma unroll
    for (int s = 0; s < NSUBS; s++) {
        const int col = s * NSUB + coloff;
        *(float2*)(out + rowg0 + col) = make_float2(sc[s][0] * inv0, sc[s][1] * inv0);
        *(float2*)(out + rowg0 + (size_t)8 * S_LEN + col) =
            make_float2(sc[s][2] * inv1, sc[s][3] * inv1);
    }
}

// ---------------------------------------------------------------------------
extern "C" void kernel_launch(void* const* d_in, const int* in_sizes, int n_in,
                              void* d_out, int out_size)
{
    const float* keys      = (const float*)d_in[0];
    const float* queries   = (const float*)d_in[1];
    const float* pos_key   = (const float*)d_in[2];
    const float* pos_query = (const float*)d_in[3];
    float* out = (float*)d_out;

    // pass 0: fp16 convert (vectorized)
    const size_t prep_total4 = (size_t)BHN * S_LEN * (KC / 4);
    prep_fp16<<<(unsigned)((prep_total4 + 255) / 256), 256>>>(keys, queries, pos_key, pos_query);

    // pass 1: fused GEMM + softmax
    cudaFuncSetAttribute(fused_attn, cudaFuncAttributeMaxDynamicSharedMemorySize, SM_TOT);
    dim3 g(S_LEN / MROWS, BHN);     // (128, 64)
    fused_attn<<<g, 512, SM_TOT>>>(out);
}

// round 11
// speedup vs baseline: 1.3183x; 1.1205x over previous
#include <cuda_runtime.h>
#include <cuda_fp16.h>
#include <cstdint>
#include <math.h>

// ---------------- problem constants ----------------
#define S_LEN 2048
#define BHN   64          // B*H
#define DQ    64
#define DP    32
#define KC    96          // concatenated K (q|pq)
#define SCALE_Q 0.125f
#define SCALE_P 0.17677669529663687f

#define MROWS 32          // rows per CTA (full 2048-wide ownership)
#define NSUB  128         // columns per subtile
#define NSUBS 16          // 2048 / 128
#define SPADB 208         // A/B smem row stride bytes (13*16B, ldmatrix-clean)
#define NSTG  3           // B ring stages per warp
#define WSTAGE 1664       // per-warp per-stage bytes (8 rows * 208)
#define WSLAB  (NSTG * WSTAGE)        // 4992 B per warp
#define SROWB  4112       // score smem row stride (4096 + 16 skew: conflict-free)

#define SM_A    0                     // A: 32*208 = 6656
#define SM_RED  6656                  // 32*16 partials (2048) + 32 sums (128)
#define SM_SC   8832                  // scores: 32 * 4112 = 131584
#define SM_B    140416                // B slabs: 16 * 4992 = 79872
#define SM_TOT  220288

// fp16 scratch: [bh][s][96]  (clamp+scale folded on A side)
__device__ __align__(16) __half g_Ah[(size_t)BHN * S_LEN * KC];
__device__ __align__(16) __half g_Bh[(size_t)BHN * S_LEN * KC];

__device__ __forceinline__ float clamp5(float x) {
    return fminf(fmaxf(x, -5.0f), 5.0f);
}

__device__ __forceinline__ uint32_t h2_to_u32(__half2 h) {
    union { __half2 h; uint32_t u; } cv;
    cv.h = h;
    return cv.u;
}

__device__ __forceinline__ uint32_t smem_u32(const void* p) {
    uint32_t a;
    asm("{ .reg .u64 t; cvta.to.shared.u64 t, %1; cvt.u32.u64 %0, t; }" : "=r"(a) : "l"(p));
    return a;
}
__device__ __forceinline__ void cp16(uint32_t dst, const void* src) {
    asm volatile("cp.async.cg.shared.global [%0], [%1], 16;" :: "r"(dst), "l"(src));
}
#define CP_COMMIT() asm volatile("cp.async.commit_group;" ::: "memory")
#define CP_WAIT1()  asm volatile("cp.async.wait_group 1;" ::: "memory")

__device__ __forceinline__ void ldsm_x4(uint32_t* r, uint32_t addr) {
    asm volatile("ldmatrix.sync.aligned.m8n8.x4.shared.b16 {%0,%1,%2,%3}, [%4];"
                 : "=r"(r[0]), "=r"(r[1]), "=r"(r[2]), "=r"(r[3]) : "r"(addr));
}
__device__ __forceinline__ void mma_fp16(float* d, const uint32_t* a, const uint32_t* b) {
    asm volatile("mma.sync.aligned.m16n8k16.row.col.f32.f16.f16.f32 "
                 "{%0,%1,%2,%3}, {%4,%5,%6,%7}, {%8,%9}, {%0,%1,%2,%3};"
                 : "+f"(d[0]), "+f"(d[1]), "+f"(d[2]), "+f"(d[3])
                 : "r"(a[0]), "r"(a[1]), "r"(a[2]), "r"(a[3]), "r"(b[0]), "r"(b[1]));
}

// ---------------------------------------------------------------------------
// Pass 0: clamp + scale + fp16 convert; 4 elements per thread (float4 loads).
// ---------------------------------------------------------------------------
__global__ __launch_bounds__(256) void prep_fp16(
    const float* __restrict__ keys, const float* __restrict__ queries,
    const float* __restrict__ pos_key, const float* __restrict__ pos_query)
{
    size_t idx4 = (size_t)blockIdx.x * blockDim.x + threadIdx.x;
    const size_t total4 = (size_t)BHN * S_LEN * (KC / 4);
    if (idx4 >= total4) return;
    size_t row = idx4 / (KC / 4);
    int c0 = (int)(idx4 % (KC / 4)) * 4;
    float4 va, vb;
    if (c0 < DQ) {
        va = *(const float4*)(queries + row * DQ + c0);
        vb = *(const float4*)(keys + row * DQ + c0);
        va.x = clamp5(va.x) * SCALE_Q; va.y = clamp5(va.y) * SCALE_Q;
        va.z = clamp5(va.z) * SCALE_Q; va.w = clamp5(va.w) * SCALE_Q;
    } else {
        va = *(const float4*)(pos_query + row * DP + (c0 - DQ));
        vb = *(const float4*)(pos_key + row * DP + (c0 - DQ));
        va.x = clamp5(va.x) * SCALE_P; va.y = clamp5(va.y) * SCALE_P;
        va.z = clamp5(va.z) * SCALE_P; va.w = clamp5(va.w) * SCALE_P;
    }
    vb.x = clamp5(vb.x); vb.y = clamp5(vb.y);
    vb.z = clamp5(vb.z); vb.w = clamp5(vb.w);
    *(__half2*)(g_Ah + row * KC + c0)     = __floats2half2_rn(va.x, va.y);
    *(__half2*)(g_Ah + row * KC + c0 + 2) = __floats2half2_rn(va.z, va.w);
    *(__half2*)(g_Bh + row * KC + c0)     = __floats2half2_rn(vb.x, vb.y);
    *(__half2*)(g_Bh + row * KC + c0 + 2) = __floats2half2_rn(vb.z, vb.w);
}

// ---------------------------------------------------------------------------
// Pass 1 (fused): 32x2048 scores -> exp (fp16 smem) -> fp32 rowsum (regs) ->
// normalized single-pass write. Warp-private 3-stage B ring; each warp does
// TWO m16 row-tiles per n8 strip (12 HMMA/iter, 4 independent chains).
// Ledger: 2 prologue commits, one commit/iter -> wait_group 1 at iter s
// guarantees stage s landed.
// ---------------------------------------------------------------------------
__global__ __launch_bounds__(512, 1) void fused_attn(float* __restrict__ out)
{
    extern __shared__ __align__(16) char smraw[];
    float* redp = (float*)(smraw + SM_RED);          // [32 rows][16 warps]
    float* rsum = redp + 32 * 16;                    // [32] inverse sums
    const uint32_t sA  = smem_u32(smraw + SM_A);
    const uint32_t sSC = smem_u32(smraw + SM_SC);

    const int tid = threadIdx.x;
    const int lane = tid & 31, warp = tid >> 5;      // 16 warps
    const int mt = blockIdx.x, bh = blockIdx.y;

    const __half* Ag = g_Ah + ((size_t)bh * S_LEN + (size_t)mt * MROWS) * KC;
    const __half* Bg = g_Bh + (size_t)bh * S_LEN * KC;

    const uint32_t slab = smem_u32(smraw + SM_B) + warp * WSLAB;

    // --- prologue: issue B stages 0,1 (per-warp groups) ---
    #pragma unroll
    for (int j = 0; j < 2; j++) {
        #pragma unroll
        for (int i = 0; i < 3; i++) {
            int f = lane + i * 32;            // 0..95
            int r = f / 12, c = f % 12;
            cp16(slab + j * WSTAGE + r * SPADB + c * 16,
                 (const char*)Bg + ((size_t)j * NSUB + warp * 8 + r) * (KC * 2) + c * 16);
        }
        CP_COMMIT();
    }

    // --- A: 32 rows x 12 chunks = 384 one-time loads ---
    if (tid < 384) {
        int row = tid / 12, c = tid % 12;
        uint4 v = *(const uint4*)((const char*)Ag + (size_t)row * (KC * 2) + c * 16);
        *(uint4*)(smraw + SM_A + row * SPADB + c * 16) = v;
    }
    __syncthreads();

    // --- A fragments: rows 0-15 (lo) and 16-31 (hi), 6 k-steps each ---
    uint32_t aLo[6][4], aHi[6][4];
    {
        const uint32_t ab = sA + (lane & 15) * SPADB + ((lane >> 4) << 3) * 2;
        #pragma unroll
        for (int k = 0; k < 6; k++) {
            ldsm_x4(aLo[k], ab + k * 32);
            ldsm_x4(aHi[k], ab + 16 * SPADB + k * 32);
        }
    }

    const int r0 = lane >> 2;                       // 0..7
    const int c2 = (lane & 3) * 2;
    const uint32_t bfoff = (lane & 7) * SPADB + (lane >> 3) * 16;
    const uint32_t scbase = sSC + (warp * 8 + c2) * 2;   // + row*SROWB + sub*256

    float s0 = 0.0f, s1 = 0.0f, s2 = 0.0f, s3 = 0.0f;

    #pragma unroll
    for (int s = 0; s < NSUBS; s++) {
        CP_WAIT1();
        __syncwarp();

        const uint32_t bb = slab + (s % NSTG) * WSTAGE + bfoff;
        uint32_t b[3][4];
        #pragma unroll
        for (int j = 0; j < 3; j++)
            ldsm_x4(b[j], bb + j * 64);

        float A0[4] = {0,0,0,0}, A1[4] = {0,0,0,0};
        float C0[4] = {0,0,0,0}, C1[4] = {0,0,0,0};
        #pragma unroll
        for (int j = 0; j < 3; j++) {
            mma_fp16(A0, aLo[2 * j],     &b[j][0]);
            mma_fp16(A1, aLo[2 * j + 1], &b[j][2]);
            mma_fp16(C0, aHi[2 * j],     &b[j][0]);
            mma_fp16(C1, aHi[2 * j + 1], &b[j][2]);
        }

        if (s + 2 < NSUBS) {
            #pragma unroll
            for (int i = 0; i < 3; i++) {
                int f = lane + i * 32;
                int r = f / 12, c = f % 12;
                cp16(slab + ((s + 2) % NSTG) * WSTAGE + r * SPADB + c * 16,
                     (const char*)Bg + ((size_t)(s + 2) * NSUB + warp * 8 + r) * (KC * 2) + c * 16);
            }
        }
        CP_COMMIT();

        // exp (MUFU) -> fp16 scores to smem; fp32 sums in regs
        float v0 = __expf(A0[0] + A1[0]), v1 = __expf(A0[1] + A1[1]);
        float v2 = __expf(A0[2] + A1[2]), v3 = __expf(A0[3] + A1[3]);
        float w0 = __expf(C0[0] + C1[0]), w1 = __expf(C0[1] + C1[1]);
        float w2 = __expf(C0[2] + C1[2]), w3 = __expf(C0[3] + C1[3]);
        s0 += v0 + v1;  s1 += v2 + v3;
        s2 += w0 + w1;  s3 += w2 + w3;

        const uint32_t scs = scbase + s * (NSUB * 2);
        asm volatile("st.shared.b32 [%0], %1;" :: "r"(scs + r0 * SROWB),
                     "r"(h2_to_u32(__floats2half2_rn(v0, v1))) : "memory");
        asm volatile("st.shared.b32 [%0], %1;" :: "r"(scs + (r0 + 8) * SROWB),
                     "r"(h2_to_u32(__floats2half2_rn(v2, v3))) : "memory");
        asm volatile("st.shared.b32 [%0], %1;" :: "r"(scs + (r0 + 16) * SROWB),
                     "r"(h2_to_u32(__floats2half2_rn(w0, w1))) : "memory");
        asm volatile("st.shared.b32 [%0], %1;" :: "r"(scs + (r0 + 24) * SROWB),
                     "r"(h2_to_u32(__floats2half2_rn(w2, w3))) : "memory");
    }

    // --- deterministic row sums ---
    s0 += __shfl_xor_sync(0xffffffffu, s0, 1);
    s0 += __shfl_xor_sync(0xffffffffu, s0, 2);
    s1 += __shfl_xor_sync(0xffffffffu, s1, 1);
    s1 += __shfl_xor_sync(0xffffffffu, s1, 2);
    s2 += __shfl_xor_sync(0xffffffffu, s2, 1);
    s2 += __shfl_xor_sync(0xffffffffu, s2, 2);
    s3 += __shfl_xor_sync(0xffffffffu, s3, 1);
    s3 += __shfl_xor_sync(0xffffffffu, s3, 2);
    if ((lane & 3) == 0) {
        redp[r0 * 16 + warp] = s0;
        redp[(r0 + 8) * 16 + warp] = s1;
        redp[(r0 + 16) * 16 + warp] = s2;
        redp[(r0 + 24) * 16 + warp] = s3;
    }
    __syncthreads();
    if (tid < MROWS) {
        float t = 0.0f;
        #pragma unroll
        for (int w = 0; w < 16; w++) t += redp[tid * 16 + w];
        rsum[tid] = 1.0f / t;
    }
    __syncthreads();

    // --- readback + normalize + single coalesced DRAM pass ---
    {
        const int row = tid >> 4;            // 0..31
        const int l16 = tid & 15;
        const float inv = rsum[row];
        const uint32_t srow = sSC + row * SROWB;
        float* orow = out + ((size_t)bh * S_LEN + (size_t)mt * MROWS + row) * S_LEN;
        #pragma unroll
        for (int i = 0; i < 16; i++) {
            const int chunk = l16 + i * 16;           // 16B = 8 halves
            uint32_t h[4];
            asm volatile("ld.shared.v4.b32 {%0,%1,%2,%3}, [%4];"
                         : "=r"(h[0]), "=r"(h[1]), "=r"(h[2]), "=r"(h[3])
                         : "r"(srow + chunk * 16));
            float2 f0 = __half22float2(*(__half2*)&h[0]);
            float2 f1 = __half22float2(*(__half2*)&h[1]);
            float2 f2 = __half22float2(*(__half2*)&h[2]);
            float2 f3 = __half22float2(*(__half2*)&h[3]);
            float4 o0 = make_float4(f0.x * inv, f0.y * inv, f1.x * inv, f1.y * inv);
            float4 o1 = make_float4(f2.x * inv, f2.y * inv, f3.x * inv, f3.y * inv);
            *(float4*)(orow + chunk * 8)     = o0;
            *(float4*)(orow + chunk * 8 + 4) = o1;
        }
    }
}

// ---------------------------------------------------------------------------
extern "C" void kernel_launch(void* const* d_in, const int* in_sizes, int n_in,
                              void* d_out, int out_size)
{
    const float* keys      = (const float*)d_in[0];
    const float* queries   = (const float*)d_in[1];
    const float* pos_key   = (const float*)d_in[2];
    const float* pos_query = (const float*)d_in[3];
    float* out = (float*)d_out;

    const size_t prep_total4 = (size_t)BHN * S_LEN * (KC / 4);
    prep_fp16<<<(unsigned)((prep_total4 + 255) / 256), 256>>>(keys, queries, pos_key, pos_query);

    cudaFuncSetAttribute(fused_attn, cudaFuncAttributeMaxDynamicSharedMemorySize, SM_TOT);
    dim3 g(S_LEN / MROWS, BHN);     // (64, 64)
    fused_attn<<<g, 512, SM_TOT>>>(out);
}